// round 17
// baseline (speedup 1.0000x reference)
#include <cuda_runtime.h>
#include <cuda_fp16.h>
#include <math.h>
#include <stdint.h>

// ---------------- problem constants ----------------
#define BB     4
#define PP     65536
#define NPTS   (BB * PP)
#define TD     32
#define HID    128
#define CD     36
#define FIN    68
#define RES    256

#define NP     64               // points per CTA
#define NTHR   256              // 8 warps: warp&1 = m-half (32 rows), warp>>1 = n-group (32 cols)
#define STRIDE 136              // padded row stride (elems) for X and W
#define ROWB   (STRIDE * 2)     // 272 B per row
#define WPLANE (128 * ROWB)     // 34816
#define HSTR   88               // H row stride (elems), K 0..79
#define HROWB  (HSTR * 2)       // 176
#define HWPL   (128 * HROWB)    // 22528: compact weight plane (K<=80)

// smem layout (bytes). H aliases X (H dies at first X write).
#define X_HI      0             // X plane (17408); H aliased (11264)
#define W_0       17408         // W buffer: fused [w_skip|w_in] compact (45056) OR one 34816 plane
#define W_OUT     62464         // w_out buffer (2176)
#define SM_BIAS   64640         // 772 floats
#define SM_COORD  67728         // 192 floats
#define SMEM_BYTES 68608

// ---------------- device scratch ----------------
__device__ __align__(16) __half g_tp[12 * RES * RES * TD];   // fp16 triplane [plane][hw][32ch]
// layout: [w_skip compact HWPL][w_in compact HWPL][w_b0,w_b1,w_a0,w_a1 WPLANE each][w_out 8*ROWB]
#define GW_HID   (2 * HWPL)                 // 45056: start of STRIDE-layout hidden weights
#define GW_OUT   (GW_HID + 4 * WPLANE)      // start of w_out
__device__ __align__(16) unsigned char g_wp[GW_OUT + 8 * ROWB];

// ---------------- helpers ----------------
__device__ __forceinline__ uint32_t smem_u32(const void* p) {
    uint32_t a;
    asm("{ .reg .u64 t; cvta.to.shared.u64 t, %1; cvt.u32.u64 %0, t; }" : "=r"(a) : "l"(p));
    return a;
}
__device__ __forceinline__ void ldsm4(uint32_t a, uint32_t r[4]) {
    asm volatile("ldmatrix.sync.aligned.m8n8.x4.shared.b16 {%0,%1,%2,%3}, [%4];"
                 : "=r"(r[0]), "=r"(r[1]), "=r"(r[2]), "=r"(r[3]) : "r"(a));
}
__device__ __forceinline__ void ldsm2(uint32_t a, uint32_t r[2]) {
    asm volatile("ldmatrix.sync.aligned.m8n8.x2.shared.b16 {%0,%1}, [%2];"
                 : "=r"(r[0]), "=r"(r[1]) : "r"(a));
}
__device__ __forceinline__ void mma16816(float d[4], const uint32_t a[4], const uint32_t b[2]) {
    asm volatile("mma.sync.aligned.m16n8k16.row.col.f32.f16.f16.f32 "
                 "{%0,%1,%2,%3}, {%4,%5,%6,%7}, {%8,%9}, {%0,%1,%2,%3};"
                 : "+f"(d[0]), "+f"(d[1]), "+f"(d[2]), "+f"(d[3])
                 : "r"(a[0]), "r"(a[1]), "r"(a[2]), "r"(a[3]), "r"(b[0]), "r"(b[1]));
}

// cp.async
__device__ __forceinline__ void cpa_stage(uint32_t dst, const unsigned char* src, int bytes, int tid) {
    for (int i = tid * 16; i < bytes; i += NTHR * 16)
        asm volatile("cp.async.cg.shared.global [%0], [%1], 16;" :: "r"(dst + i), "l"(src + i) : "memory");
}
#define CPA_COMMIT()  asm volatile("cp.async.commit_group;" ::: "memory")
#define CPA_WAIT0()   asm volatile("cp.async.wait_group 0;" ::: "memory")

// ---------------- merged prep kernel ----------------
#define TP_BLKS (12 * 512)
#define WP_TOT  (2 * 128 * HSTR + 4 * 128 * STRIDE + 8 * STRIDE)   // 93248
__global__ void prep_all_kernel(const float* __restrict__ tri,
                                const float* __restrict__ w_in,
                                const float* __restrict__ w_skip,
                                const float* __restrict__ w_before,
                                const float* __restrict__ w_after,
                                const float* __restrict__ w_out) {
    __shared__ float t[32 * 129 + 4];
    const int blk = blockIdx.x;
    const int tid = threadIdx.x;
    if (blk < TP_BLKS) {
        const int n   = blk >> 9;
        const int hw0 = (blk & 511) * 128;
        const int c   = tid >> 3;
        const int h8  = tid & 7;
        const float* src = tri + (size_t)(n * 32 + c) * 65536 + hw0;
        #pragma unroll
        for (int i = 0; i < 4; i++) {
            int hw = i * 32 + h8 * 4;
            float4 v = *(const float4*)(src + hw);
            float* tr = t + c * 129 + hw;
            tr[0] = v.x; tr[1] = v.y; tr[2] = v.z; tr[3] = v.w;
        }
        __syncthreads();
        #pragma unroll
        for (int i = 0; i < 2; i++) {
            int e  = tid + 256 * i;
            int hw = e >> 2, c8 = e & 3;
            const float* tc = t + (8 * c8) * 129 + hw;
            __half2 h0 = __floats2half2_rn(tc[0 * 129], tc[1 * 129]);
            __half2 h1 = __floats2half2_rn(tc[2 * 129], tc[3 * 129]);
            __half2 h2 = __floats2half2_rn(tc[4 * 129], tc[5 * 129]);
            __half2 h3 = __floats2half2_rn(tc[6 * 129], tc[7 * 129]);
            uint4 v = make_uint4(*(uint32_t*)&h0, *(uint32_t*)&h1,
                                 *(uint32_t*)&h2, *(uint32_t*)&h3);
            *(uint4*)(g_tp + ((size_t)n * 65536 + hw0 + hw) * 32 + c8 * 8) = v;
        }
        return;
    }
    int idx = (blk - TP_BLKS) * 256 + tid;
    if (idx >= WP_TOT) return;
    const int HC = 2 * 128 * HSTR;         // compact region elems
    const int HN = 4 * 128 * STRIDE;       // hidden STRIDE region elems
    float v = 0.0f;
    size_t off;
    if (idx < HC) {
        int slot = idx / (128 * HSTR);
        int e = idx % (128 * HSTR);
        int o = e / HSTR, k = e % HSTR;
        if (k < FIN) v = (slot == 0) ? w_skip[o * FIN + k] : w_in[o * FIN + k];
        off = (size_t)slot * HWPL + (size_t)(o * HSTR + k) * 2;
    } else if (idx < HC + HN) {
        int r = idx - HC;
        int l = r / (128 * STRIDE);
        int e = r % (128 * STRIDE);
        int o = e / STRIDE, k = e % STRIDE;
        if (k < HID)
            v = (l < 2) ? w_before[l * HID * HID + o * HID + k]
                        : w_after[(l - 2) * HID * HID + o * HID + k];
        off = (size_t)GW_HID + (size_t)l * WPLANE + (size_t)(o * STRIDE + k) * 2;
    } else {
        int e = idx - HC - HN;
        int o = e / STRIDE, k = e % STRIDE;
        if (o < 4 && k < HID) v = w_out[o * HID + k];
        off = (size_t)GW_OUT + (size_t)(o * STRIDE + k) * 2;
    }
    *(__half*)(g_wp + off) = __float2half_rn(v);
}

// ---------------- MMA layer ----------------
// Warp: 32 M-rows (two 16-row subtiles, A16 bytes apart) x 4 n-tiles (32 neurons).
// B16 = byte stride between the warp's two B n-tile pairs (16 rows of B).
template <int KS, int A16, int B16>
__device__ __forceinline__ void mma_layer(uint32_t aA, uint32_t bB4, float D[8][4]) {
    #pragma unroll
    for (int i = 0; i < 8; i++) { D[i][0] = 0.f; D[i][1] = 0.f; D[i][2] = 0.f; D[i][3] = 0.f; }
    #pragma unroll
    for (int k = 0; k < KS; k++) {
        uint32_t A0[4], A1[4];
        ldsm4(aA + k * 32, A0);
        ldsm4(aA + A16 + k * 32, A1);
        #pragma unroll
        for (int p = 0; p < 2; p++) {
            uint32_t Bh[4];
            ldsm4(bB4 + p * B16 + k * 32, Bh);
            mma16816(D[p * 2],         A0, Bh);
            mma16816(D[p * 2 + 1],     A0, Bh + 2);
            mma16816(D[4 + p * 2],     A1, Bh);
            mma16816(D[4 + p * 2 + 1], A1, Bh + 2);
        }
    }
}

// single n-tile (output layer), 16 rows
template <int KS>
__device__ __forceinline__ void mma_layer1(uint32_t aA, uint32_t bB2, float d[4]) {
    d[0] = d[1] = d[2] = d[3] = 0.f;
    #pragma unroll
    for (int k = 0; k < KS; k++) {
        uint32_t Ah[4], Bh[2];
        ldsm4(aA + k * 32, Ah);
        ldsm2(bB2 + k * 32, Bh);
        mma16816(d, Ah, Bh);
    }
}

// pack skip: u[16] = fp16x2 of relu(D + bs)
__device__ __forceinline__ void pack_skip(const float D[8][4], const float* bs,
                                          int tig, int colb, uint32_t u[16]) {
    #pragma unroll
    for (int idx = 0; idx < 8; idx++) {
        int ntl = idx & 3;
        int c0 = colb + ntl * 8 + 2 * tig;
        float b0 = bs[c0], b1 = bs[c0 + 1];
        float x0 = fmaxf(D[idx][0] + b0, 0.f), x1 = fmaxf(D[idx][1] + b1, 0.f);
        float x2 = fmaxf(D[idx][2] + b0, 0.f), x3 = fmaxf(D[idx][3] + b1, 0.f);
        __half2 h0 = __floats2half2_rn(x0, x1);
        __half2 h1 = __floats2half2_rn(x2, x3);
        u[idx * 2]     = *(uint32_t*)&h0;
        u[idx * 2 + 1] = *(uint32_t*)&h1;
    }
}

// epilogue: bias + relu (+ add pre-relu'd skip u), fp16 pack, store into X.
template <bool SK>
__device__ __forceinline__ void epi(unsigned char* sm, const float D[8][4],
                                    const uint32_t u[16], const float* bd,
                                    int pBase, int tig, int colb) {
    #pragma unroll
    for (int mi = 0; mi < 2; mi++) {
        const int rowA = (pBase + mi * 16) * ROWB;
        const int rowB = rowA + 8 * ROWB;
        #pragma unroll
        for (int ntl = 0; ntl < 4; ntl++) {
            int idx = mi * 4 + ntl;
            int c0 = colb + ntl * 8 + 2 * tig;
            float b0 = bd[c0], b1 = bd[c0 + 1];
            float x0 = fmaxf(D[idx][0] + b0, 0.f), x1 = fmaxf(D[idx][1] + b1, 0.f);
            float x2 = fmaxf(D[idx][2] + b0, 0.f), x3 = fmaxf(D[idx][3] + b1, 0.f);
            if (SK) {
                __half2 s0 = *(__half2*)&u[idx * 2];
                __half2 s1 = *(__half2*)&u[idx * 2 + 1];
                x0 += __low2float(s0);  x1 += __high2float(s0);
                x2 += __low2float(s1);  x3 += __high2float(s1);
            }
            __half2 h0 = __floats2half2_rn(x0, x1);
            __half2 h1 = __floats2half2_rn(x2, x3);
            int off = c0 * 2;
            *(uint32_t*)(sm + X_HI + rowA + off) = *(uint32_t*)&h0;
            *(uint32_t*)(sm + X_HI + rowB + off) = *(uint32_t*)&h1;
        }
    }
}

// ---------------- main decoder kernel ----------------
__global__ void __launch_bounds__(NTHR, 3)
decoder_kernel(const float* __restrict__ coords,
               const float* __restrict__ b_in,
               const float* __restrict__ b_skip,
               const float* __restrict__ b_before,
               const float* __restrict__ b_after,
               const float* __restrict__ b_out,
               float* __restrict__ out) {
    extern __shared__ unsigned char sm[];
    const uint32_t sb = smem_u32(sm);
    const int tid  = threadIdx.x;
    const int lane = tid & 31;
    const int warp = tid >> 5;
    const int mt   = warp & 1;      // m-half (32 rows)
    const int ng   = warp >> 1;     // n-group (32 neurons)
    const int base = blockIdx.x * NP;

    float* bS = (float*)(sm + SM_BIAS);
    float* cS = (float*)(sm + SM_COORD);

    // stage [w_skip|w_in] compact + w_out immediately (overlaps with gather)
    cpa_stage(sb + W_0, g_wp, 2 * HWPL, tid);
    cpa_stage(sb + W_OUT, g_wp + GW_OUT, 8 * ROWB, tid);
    CPA_COMMIT();

    // coords + biases
    for (int i = tid; i < NP * 3; i += NTHR) cS[i] = coords[base * 3 + i];
    for (int i = tid; i < 772; i += NTHR) {
        float v;
        if (i < 128)      v = b_in[i];
        else if (i < 256) v = b_skip[i - 128];
        else if (i < 512) v = b_before[i - 256];
        else if (i < 768) v = b_after[i - 512];
        else              v = b_out[i - 768];
        bS[i] = v;
    }
    // zero H pad cols 68..79: 64 rows x 12 cols, 4 threads/row
    {
        int p = tid >> 2, q = tid & 3;
        #pragma unroll
        for (int j = 0; j < 3; j++) {
            int k = FIN + q * 3 + j;
            *(uint16_t*)(sm + X_HI + (p * HSTR + k) * 2) = 0;
        }
    }
    __syncthreads();

    // ---- gather + freq encode -> H (fp16, stride 88): 4 threads/point ----
    {
        const int p = tid >> 2;
        const int q = tid & 3;
        const float c0 = cS[p * 3 + 0];
        const float c1 = cS[p * 3 + 1];
        const float c2 = cS[p * 3 + 2];
        const float nrm[3] = {(c0 + 1.0f) * 0.5f, (c1 + 1.0f) * 0.5f, (c2 + 1.0f) * 0.5f};

        // freq encode: thread q<3 handles dim q (12 contiguous halfs = 3 uint2 stores)
        if (q < 3) {
            float s[6], c[6];
            #pragma unroll
            for (int k = 0; k < 6; k++) {
                float freq = 3.14159265358979f * (float)(1 << k);
                __sincosf(nrm[q] * freq, &s[k], &c[k]);
            }
            __half2 hs0 = __floats2half2_rn(s[0], s[1]);
            __half2 hs1 = __floats2half2_rn(s[2], s[3]);
            __half2 hs2 = __floats2half2_rn(s[4], s[5]);
            __half2 hc0 = __floats2half2_rn(c[0], c[1]);
            __half2 hc1 = __floats2half2_rn(c[2], c[3]);
            __half2 hc2 = __floats2half2_rn(c[4], c[5]);
            unsigned char* dst = sm + X_HI + (p * HSTR + q * 12) * 2;
            *(uint2*)(dst)      = make_uint2(*(uint32_t*)&hs0, *(uint32_t*)&hs1);
            *(uint2*)(dst + 8)  = make_uint2(*(uint32_t*)&hs2, *(uint32_t*)&hc0);
            *(uint2*)(dst + 16) = make_uint2(*(uint32_t*)&hc1, *(uint32_t*)&hc2);
        }

        const int b = (base + p) >> 16;
        const float gpx[3] = {c0, c0, c1};
        const float gpy[3] = {c1, c2, c2};
        float acc[8];
        #pragma unroll
        for (int j = 0; j < 8; j++) acc[j] = 0.0f;

        #pragma unroll
        for (int pl = 0; pl < 3; pl++) {
            float ix = (gpx[pl] + 1.0f) * 127.5f;
            float iy = (gpy[pl] + 1.0f) * 127.5f;
            float x0f = floorf(ix), y0f = floorf(iy);
            float fx = ix - x0f, fy = iy - y0f;
            int x0 = min(max((int)x0f, 0), RES - 2);
            int y0 = min(max((int)y0f, 0), RES - 2);
            float w00 = (1.0f - fx) * (1.0f - fy);
            float w10 = fx * (1.0f - fy);
            float w01 = (1.0f - fx) * fy;
            float w11 = fx * fy;
            const __half* bp = g_tp + ((size_t)(b * 3 + pl) * (RES * RES) + y0 * RES + x0) * TD + q * 8;
            uint4 r00 = *(const uint4*)(bp);
            uint4 r10 = *(const uint4*)(bp + TD);
            uint4 r01 = *(const uint4*)(bp + RES * TD);
            uint4 r11 = *(const uint4*)(bp + RES * TD + TD);
            #pragma unroll
            for (int j = 0; j < 4; j++) {
                float2 f00 = __half22float2(((const __half2*)&r00)[j]);
                float2 f10 = __half22float2(((const __half2*)&r10)[j]);
                float2 f01 = __half22float2(((const __half2*)&r01)[j]);
                float2 f11 = __half22float2(((const __half2*)&r11)[j]);
                acc[2 * j]     += w00 * f00.x + w10 * f10.x + w01 * f01.x + w11 * f11.x;
                acc[2 * j + 1] += w00 * f00.y + w10 * f10.y + w01 * f01.y + w11 * f11.y;
            }
        }
        // packed stores: base offset = p*176 + 72 + q*16, 8-byte aligned -> two uint2 stores
        {
            __half2 h0 = __floats2half2_rn(acc[0], acc[1]);
            __half2 h1 = __floats2half2_rn(acc[2], acc[3]);
            __half2 h2 = __floats2half2_rn(acc[4], acc[5]);
            __half2 h3 = __floats2half2_rn(acc[6], acc[7]);
            unsigned char* dst = sm + X_HI + (p * HSTR + CD + q * 8) * 2;
            *(uint2*)(dst)     = make_uint2(*(uint32_t*)&h0, *(uint32_t*)&h1);
            *(uint2*)(dst + 8) = make_uint2(*(uint32_t*)&h2, *(uint32_t*)&h3);
        }
    }

    // per-thread fragment addresses
    const int rowM = mt * 32 + (lane & 15);
    const uint32_t aX = sb + X_HI + (uint32_t)((rowM * STRIDE + (lane >> 4) * 8) * 2);
    const uint32_t aH = sb + X_HI + (uint32_t)((rowM * HSTR + (lane >> 4) * 8) * 2);
    // compact (HSTR) B base for skip / in weights
    const uint32_t bH4 = sb + W_0 + (uint32_t)(ng * 32 * HROWB) +
        (uint32_t)((((lane & 7) + (lane >> 4) * 8) * HSTR + ((lane >> 3) & 1) * 8) * 2);
    // STRIDE B base for hidden layers
    const uint32_t bW4 = sb + W_0 + (uint32_t)(ng * 32 * ROWB) +
        (uint32_t)((((lane & 7) + (lane >> 4) * 8) * STRIDE + ((lane >> 3) & 1) * 8) * 2);

    const int g     = lane >> 2;
    const int tig   = lane & 3;
    const int pBase = mt * 32 + g;
    const int colb  = ng * 32;

    float D[8][4];
    uint32_t u[16];

    // ---- SKIP + L1 fused phase (both weights resident, no intervening barrier) ----
    CPA_WAIT0();
    __syncthreads();
    mma_layer<5, 16 * HROWB, 16 * HROWB>(aH, bH4, D);          // D = Wskip h
    pack_skip(D, bS + 128, tig, colb, u);
    mma_layer<5, 16 * HROWB, 16 * HROWB>(aH, bH4 + HWPL, D);   // D = Win h
    __syncthreads();                   // H + W_0 reads complete
    cpa_stage(sb + W_0, g_wp + GW_HID + 0 * WPLANE, WPLANE, tid); CPA_COMMIT();  // w_b0
    epi<false>(sm, D, u, bS + 0, pBase, tig, colb);            // x1 -> X (H dead)
    CPA_WAIT0();
    __syncthreads();

    // ---- L2: D = W0 x1 ----
    mma_layer<8, 16 * ROWB, 16 * ROWB>(aX, bW4, D);
    __syncthreads();
    cpa_stage(sb + W_0, g_wp + GW_HID + 1 * WPLANE, WPLANE, tid); CPA_COMMIT();  // w_b1
    epi<false>(sm, D, u, bS + 256, pBase, tig, colb);          // x2 -> X
    CPA_WAIT0();
    __syncthreads();

    // ---- L3: D = W1 x2 ; x4 = relu(D+b) + u ----
    mma_layer<8, 16 * ROWB, 16 * ROWB>(aX, bW4, D);
    __syncthreads();
    cpa_stage(sb + W_0, g_wp + GW_HID + 2 * WPLANE, WPLANE, tid); CPA_COMMIT();  // w_a0
    epi<true>(sm, D, u, bS + 384, pBase, tig, colb);           // x4 -> X
    CPA_WAIT0();
    __syncthreads();

    // ---- L4: D = W2 x4 ----
    mma_layer<8, 16 * ROWB, 16 * ROWB>(aX, bW4, D);
    __syncthreads();
    cpa_stage(sb + W_0, g_wp + GW_HID + 3 * WPLANE, WPLANE, tid); CPA_COMMIT();  // w_a1
    epi<false>(sm, D, u, bS + 512, pBase, tig, colb);          // x5 -> X
    CPA_WAIT0();
    __syncthreads();

    // ---- L5: D = W3 x5 ----
    mma_layer<8, 16 * ROWB, 16 * ROWB>(aX, bW4, D);
    __syncthreads();
    epi<false>(sm, D, u, bS + 640, pBase, tig, colb);          // x6 -> X
    __syncthreads();

    // ---- L6: out = Wout x6 (warps 0..3, rows warp*16..+15; cols 0..3 valid) ----
    if (warp < 4) {
        const uint32_t aX6 = sb + X_HI +
            (uint32_t)(((warp * 16 + (lane & 15)) * STRIDE + (lane >> 4) * 8) * 2);
        const uint32_t bO2 = sb + W_OUT +
            (uint32_t)(((lane & 7) * STRIDE + ((lane >> 3) & 1) * 8) * 2);
        float Do[4];
        mma_layer1<8>(aX6, bO2, Do);
        const int pA  = warp * 16 + g;
        const int pB  = pA + 8;
        const int gpA = base + pA, gpB = base + pB;
        if (tig == 0) {
            float v0 = Do[0] + bS[768], v1 = Do[1] + bS[769];
            float v2 = Do[2] + bS[768], v3 = Do[3] + bS[769];
            out[gpA * 3 + 0] = 1.0f / (1.0f + __expf(-v0));
            out[gpA * 3 + 1] = 1.0f / (1.0f + __expf(-v1));
            out[gpB * 3 + 0] = 1.0f / (1.0f + __expf(-v2));
            out[gpB * 3 + 1] = 1.0f / (1.0f + __expf(-v3));
        } else if (tig == 1) {
            float v0 = Do[0] + bS[770], v1 = Do[1] + bS[771];
            float v2 = Do[2] + bS[770], v3 = Do[3] + bS[771];
            out[gpA * 3 + 2] = 1.0f / (1.0f + __expf(-v0));
            out[gpB * 3 + 2] = 1.0f / (1.0f + __expf(-v2));
            float a0 = cS[pA * 3 + 0], a1 = cS[pA * 3 + 1], a2 = cS[pA * 3 + 2];
            bool selA = (a0 > -1.0f) && (a0 < 1.0f) && (a1 > -1.0f) && (a1 < 1.0f) &&
                        (a2 > -1.0f) && (a2 < 1.0f);
            float b0 = cS[pB * 3 + 0], b1 = cS[pB * 3 + 1], b2 = cS[pB * 3 + 2];
            bool selB = (b0 > -1.0f) && (b0 < 1.0f) && (b1 > -1.0f) && (b1 < 1.0f) &&
                        (b2 > -1.0f) && (b2 < 1.0f);
            out[3 * NPTS + gpA] = selA ? __expf(v1 - 1.0f) : 0.0f;
            out[3 * NPTS + gpB] = selB ? __expf(v3 - 1.0f) : 0.0f;
        }
    }
}

// ---------------- launch ----------------
extern "C" void kernel_launch(void* const* d_in, const int* in_sizes, int n_in,
                              void* d_out, int out_size) {
    const float* triplane = (const float*)d_in[0];
    const float* coords   = (const float*)d_in[1];
    const float* w_in     = (const float*)d_in[2];
    const float* b_in     = (const float*)d_in[3];
    const float* w_skip   = (const float*)d_in[4];
    const float* b_skip   = (const float*)d_in[5];
    const float* w_before = (const float*)d_in[6];
    const float* b_before = (const float*)d_in[7];
    const float* w_after  = (const float*)d_in[8];
    const float* b_after  = (const float*)d_in[9];
    const float* w_out    = (const float*)d_in[10];
    const float* b_out    = (const float*)d_in[11];
    float* out = (float*)d_out;

    static bool attr_set = false;
    if (!attr_set) {
        cudaFuncSetAttribute(decoder_kernel,
                             cudaFuncAttributeMaxDynamicSharedMemorySize, SMEM_BYTES);
        attr_set = true;
    }

    const int wp_blks = (WP_TOT + 255) / 256;
    prep_all_kernel<<<TP_BLKS + wp_blks, 256>>>(
        triplane, w_in, w_skip, w_before, w_after, w_out);
    decoder_kernel<<<NPTS / NP, NTHR, SMEM_BYTES>>>(
        coords, b_in, b_skip, b_before, b_after, b_out, out);
}